// round 1
// baseline (speedup 1.0000x reference)
#include <cuda_runtime.h>
#include <cstdint>

// Fixed problem shape (registry problem is fixed-shape; edge counts taken from in_sizes).
#define NCC   100000   // n_coarse
#define CDIM  64

typedef unsigned long long u64;

// ---------------- scratch (static __device__ arrays; no allocation) ----------------
__device__ float g_xc[(size_t)NCC * CDIM];  // pooled coarse features / layer-2 output
__device__ float g_t [(size_t)NCC * CDIM];  // A @ W_nb (neighbor-transformed features)
__device__ float g_h [(size_t)NCC * CDIM];  // A @ W_root + b (accumulates messages)

// ---------------- helpers ----------------
__device__ __forceinline__ u64 pack2(float x) {
    u64 r;
    asm("mov.b64 %0, {%1, %1};" : "=l"(r) : "f"(x));
    return r;
}
__device__ __forceinline__ void fma2(u64& d, u64 a, u64 b) {
    // packed 2-wide fp32 FMA (SASS FFMA2) — 2x FFMA issue throughput
    asm("fma.rn.f32x2 %0, %1, %2, %0;" : "+l"(d) : "l"(a), "l"(b));
}

// ---------------- zero init ----------------
__global__ void zero_kernel(float4* __restrict__ p, int n4) {
    int i = blockIdx.x * blockDim.x + threadIdx.x;
    if (i < n4) p[i] = make_float4(0.f, 0.f, 0.f, 0.f);
}

// ---------------- weighted scatter-add: out[dst] += feat[src] * w ----------------
// 16 threads per edge, one float4 each. Vector reduction to L2 (no return value).
__global__ void __launch_bounds__(256) scatter_w(
    const float* __restrict__ feat,
    const int*   __restrict__ esrc,
    const int*   __restrict__ edst,
    const float* __restrict__ eattr,
    float*       __restrict__ out,
    int E)
{
    int idx = blockIdx.x * blockDim.x + threadIdx.x;
    int e = idx >> 4;
    if (e >= E) return;
    int q = (idx & 15) << 2;           // float offset within row (0,4,...,60)
    int s = __ldg(esrc + e);
    int d = __ldg(edst + e);
    float w = __ldg(eattr + e);

    float4 v = *reinterpret_cast<const float4*>(feat + (size_t)s * CDIM + q);
    v.x *= w; v.y *= w; v.z *= w; v.w *= w;

    float* p = out + (size_t)d * CDIM + q;
    asm volatile("red.global.add.v4.f32 [%0], {%1, %2, %3, %4};"
                 :: "l"(p), "f"(v.x), "f"(v.y), "f"(v.z), "f"(v.w)
                 : "memory");
}

// ---------------- fused dual GEMM: T = A@Wn ; H = A@Wr + bias ----------------
// 256 threads/block, 32 rows/block, 8 threads per row, each thread does 8 cols
// of both outputs (16 fp32 accumulators = 8 packed f32x2).
__global__ void __launch_bounds__(256) dual_gemm(
    const float* __restrict__ A,
    const float* __restrict__ Wn,
    const float* __restrict__ Wr,
    const float* __restrict__ bias,
    float* __restrict__ T,
    float* __restrict__ H,
    int N)
{
    __shared__ float sWn[CDIM * CDIM];
    __shared__ float sWr[CDIM * CDIM];
    __shared__ float sA[32 * 68];      // stride 68 floats: 16B aligned, bank-conflict-free

    const int t = threadIdx.x;

    // load both weight matrices (4096 floats each) with float4
    {
        const float4* Wn4 = reinterpret_cast<const float4*>(Wn);
        const float4* Wr4 = reinterpret_cast<const float4*>(Wr);
        float4* sWn4 = reinterpret_cast<float4*>(sWn);
        float4* sWr4 = reinterpret_cast<float4*>(sWr);
#pragma unroll
        for (int i = 0; i < 4; i++) {
            sWn4[t + 256 * i] = Wn4[t + 256 * i];
            sWr4[t + 256 * i] = Wr4[t + 256 * i];
        }
    }

    // load A tile: thread t loads row t/8, 8 floats at col (t%8)*8
    const int rowBase = blockIdx.x * 32;
    const int lr = t >> 3;
    const int lc = (t & 7) * 8;
    {
        const int grow = rowBase + lr;
        float4 a0, a1;
        if (grow < N) {
            a0 = *reinterpret_cast<const float4*>(A + (size_t)grow * CDIM + lc);
            a1 = *reinterpret_cast<const float4*>(A + (size_t)grow * CDIM + lc + 4);
        } else {
            a0 = make_float4(0.f, 0.f, 0.f, 0.f);
            a1 = a0;
        }
        *reinterpret_cast<float4*>(sA + lr * 68 + lc) = a0;
        *reinterpret_cast<float4*>(sA + lr * 68 + lc + 4) = a1;
    }
    __syncthreads();

    const int r  = t >> 3;        // local row
    const int c0 = (t & 7) * 8;   // output col group

    u64 accT[4], accR[4];
    {
        const u64* b2 = reinterpret_cast<const u64*>(bias + c0);
#pragma unroll
        for (int i = 0; i < 4; i++) { accT[i] = 0ull; accR[i] = b2[i]; }
    }

    const float4* sA4 = reinterpret_cast<const float4*>(sA + r * 68);
#pragma unroll
    for (int k4 = 0; k4 < 16; k4++) {
        float4 a4 = sA4[k4];
#pragma unroll
        for (int j = 0; j < 4; j++) {
            const int k = k4 * 4 + j;
            float ak = (j == 0) ? a4.x : (j == 1) ? a4.y : (j == 2) ? a4.z : a4.w;
            u64 ap = pack2(ak);
            const u64* wn = reinterpret_cast<const u64*>(sWn + k * CDIM + c0);
            const u64* wr = reinterpret_cast<const u64*>(sWr + k * CDIM + c0);
            fma2(accT[0], ap, wn[0]);
            fma2(accT[1], ap, wn[1]);
            fma2(accT[2], ap, wn[2]);
            fma2(accT[3], ap, wn[3]);
            fma2(accR[0], ap, wr[0]);
            fma2(accR[1], ap, wr[1]);
            fma2(accR[2], ap, wr[2]);
            fma2(accR[3], ap, wr[3]);
        }
    }

    const int grow = rowBase + r;
    if (grow < N) {
        ulonglong2 t0, t1, r0, r1;
        t0.x = accT[0]; t0.y = accT[1]; t1.x = accT[2]; t1.y = accT[3];
        r0.x = accR[0]; r0.y = accR[1]; r1.x = accR[2]; r1.y = accR[3];
        *reinterpret_cast<ulonglong2*>(T + (size_t)grow * CDIM + c0)     = t0;
        *reinterpret_cast<ulonglong2*>(T + (size_t)grow * CDIM + c0 + 4) = t1;
        *reinterpret_cast<ulonglong2*>(H + (size_t)grow * CDIM + c0)     = r0;
        *reinterpret_cast<ulonglong2*>(H + (size_t)grow * CDIM + c0 + 4) = r1;
    }
}

// ---------------- launch ----------------
extern "C" void kernel_launch(void* const* d_in, const int* in_sizes, int n_in,
                              void* d_out, int out_size)
{
    const float* x    = (const float*)d_in[0];
    const float* W1r  = (const float*)d_in[1];
    const float* W1n  = (const float*)d_in[2];
    const float* b1   = (const float*)d_in[3];
    const float* W2r  = (const float*)d_in[4];
    const float* W2n  = (const float*)d_in[5];
    const float* b2   = (const float*)d_in[6];
    const int*   psrc = (const int*)d_in[7];
    const int*   pdst = (const int*)d_in[8];
    const float* patt = (const float*)d_in[9];
    const int*   csrc = (const int*)d_in[10];
    const int*   cdst = (const int*)d_in[11];
    const float* catt = (const float*)d_in[12];
    const int*   usrc = (const int*)d_in[13];
    const int*   udst = (const int*)d_in[14];
    const float* uatt = (const float*)d_in[15];

    const int Ep = in_sizes[7];
    const int Ec = in_sizes[10];
    const int Eu = in_sizes[13];

    float* out = (float*)d_out;

    float *xc, *tb, *hb;
    cudaGetSymbolAddress((void**)&xc, g_xc);
    cudaGetSymbolAddress((void**)&tb, g_t);
    cudaGetSymbolAddress((void**)&hb, g_h);

    const int xc4  = NCC * CDIM / 4;
    const int out4 = out_size / 4;

    // zero accumulators
    zero_kernel<<<(xc4 + 255) / 256, 256>>>((float4*)xc, xc4);
    zero_kernel<<<(out4 + 255) / 256, 256>>>((float4*)out, out4);

    // pool: xc = segsum(x[psrc] * patt, pdst)
    scatter_w<<<(int)(((long long)Ep * 16 + 255) / 256), 256>>>(x, psrc, pdst, patt, xc, Ep);

    // layer 1: t = xc@W1n ; h = xc@W1r + b1 ; h += segsum(t[csrc]*catt, cdst)
    dual_gemm<<<(NCC + 31) / 32, 256>>>(xc, W1n, W1r, b1, tb, hb, NCC);
    scatter_w<<<(int)(((long long)Ec * 16 + 255) / 256), 256>>>(tb, csrc, cdst, catt, hb, Ec);

    // layer 2: t = h@W2n ; h2(=xc buf) = h@W2r + b2 ; h2 += segsum(t[csrc]*catt, cdst)
    dual_gemm<<<(NCC + 31) / 32, 256>>>(hb, W2n, W2r, b2, tb, xc, NCC);
    scatter_w<<<(int)(((long long)Ec * 16 + 255) / 256), 256>>>(tb, csrc, cdst, catt, xc, Ec);

    // unpool: out = segsum(h2[usrc]*uatt, udst)
    scatter_w<<<(int)(((long long)Eu * 16 + 255) / 256), 256>>>(xc, usrc, udst, uatt, out, Eu);
}

// round 2
// speedup vs baseline: 1.5072x; 1.5072x over previous
#include <cuda_runtime.h>
#include <cstdint>

#define NCC   100000   // n_coarse
#define CDIM  64

typedef unsigned long long u64;

// ---------------- scratch ----------------
__device__ float g_xc[(size_t)NCC * CDIM];
__device__ float g_t [(size_t)NCC * CDIM];
__device__ float g_h [(size_t)NCC * CDIM];

// ---------------- helpers ----------------
__device__ __forceinline__ u64 pack2(float x) {
    u64 r;
    asm("mov.b64 %0, {%1, %1};" : "=l"(r) : "f"(x));
    return r;
}
__device__ __forceinline__ void fma2(u64& d, u64 a, u64 b) {
    asm("fma.rn.f32x2 %0, %1, %2, %0;" : "+l"(d) : "l"(a), "l"(b));
}

// ---------------- zero init ----------------
__global__ void zero_kernel(float4* __restrict__ p, int n4) {
    int i = blockIdx.x * blockDim.x + threadIdx.x;
    if (i < n4) p[i] = make_float4(0.f, 0.f, 0.f, 0.f);
}

// ---------------- weighted scatter-add: out[dst] += feat[src] * w ----------------
__global__ void __launch_bounds__(256) scatter_w(
    const float* __restrict__ feat,
    const int*   __restrict__ esrc,
    const int*   __restrict__ edst,
    const float* __restrict__ eattr,
    float*       __restrict__ out,
    int E)
{
    int idx = blockIdx.x * blockDim.x + threadIdx.x;
    int e = idx >> 4;
    if (e >= E) return;
    int q = (idx & 15) << 2;
    int s = __ldg(esrc + e);
    int d = __ldg(edst + e);
    float w = __ldg(eattr + e);

    float4 v = *reinterpret_cast<const float4*>(feat + (size_t)s * CDIM + q);
    v.x *= w; v.y *= w; v.z *= w; v.w *= w;

    float* p = out + (size_t)d * CDIM + q;
    asm volatile("red.global.add.v4.f32 [%0], {%1, %2, %3, %4};"
                 :: "l"(p), "f"(v.x), "f"(v.y), "f"(v.z), "f"(v.w)
                 : "memory");
}

// ---------------- fused dual GEMM with 4-row register blocking ----------------
// Block: 256 threads, tile = 128 rows x 64 cols.
// Thread t: rows r0 = (t>>3)*4 .. +3, cols c0 = (t&7)*8 .. +7, for BOTH outputs.
// 64 fp32 accumulators per thread = 32 packed f32x2. Weight smem reads are
// amortized over 4 rows -> 32 FFMA2 per 128B of weight LDS (was 8).
#define ROWS_PER_BLK 128
#define SA_STRIDE    68

__global__ void __launch_bounds__(256, 2) dual_gemm(
    const float* __restrict__ A,
    const float* __restrict__ Wn,
    const float* __restrict__ Wr,
    const float* __restrict__ bias,
    float* __restrict__ T,
    float* __restrict__ H,
    int N)
{
    __shared__ float sWn[CDIM * CDIM];
    __shared__ float sWr[CDIM * CDIM];
    __shared__ float sA[ROWS_PER_BLK * SA_STRIDE];

    const int t = threadIdx.x;

    // load both weight matrices (4096 floats each) with float4
    {
        const float4* Wn4 = reinterpret_cast<const float4*>(Wn);
        const float4* Wr4 = reinterpret_cast<const float4*>(Wr);
        float4* sWn4 = reinterpret_cast<float4*>(sWn);
        float4* sWr4 = reinterpret_cast<float4*>(sWr);
#pragma unroll
        for (int i = 0; i < 4; i++) {
            sWn4[t + 256 * i] = Wn4[t + 256 * i];
            sWr4[t + 256 * i] = Wr4[t + 256 * i];
        }
    }

    // load A tile: 128 rows x 64 floats = 2048 float4; 8 float4 per thread.
    const int rowBase = blockIdx.x * ROWS_PER_BLK;
#pragma unroll
    for (int i = 0; i < 8; i++) {
        int idx = t + 256 * i;          // float4 index within tile
        int row = idx >> 4;             // 16 float4 per row
        int kc  = (idx & 15) * 4;
        float4 a;
        if (rowBase + row < N)
            a = *reinterpret_cast<const float4*>(A + (size_t)(rowBase + row) * CDIM + kc);
        else
            a = make_float4(0.f, 0.f, 0.f, 0.f);
        *reinterpret_cast<float4*>(sA + row * SA_STRIDE + kc) = a;
    }
    __syncthreads();

    const int c0 = (t & 7) * 8;
    const int r0 = (t >> 3) * 4;

    u64 accT[4][4], accR[4][4];
    {
        const u64* b2 = reinterpret_cast<const u64*>(bias + c0);
        u64 bv[4];
#pragma unroll
        for (int j = 0; j < 4; j++) bv[j] = b2[j];
#pragma unroll
        for (int r = 0; r < 4; r++)
#pragma unroll
            for (int j = 0; j < 4; j++) { accT[r][j] = 0ull; accR[r][j] = bv[j]; }
    }

#pragma unroll 8
    for (int k = 0; k < CDIM; k++) {
        // A values for this thread's 4 rows (broadcast-friendly scalar LDS)
        u64 a0 = pack2(sA[(r0 + 0) * SA_STRIDE + k]);
        u64 a1 = pack2(sA[(r0 + 1) * SA_STRIDE + k]);
        u64 a2 = pack2(sA[(r0 + 2) * SA_STRIDE + k]);
        u64 a3 = pack2(sA[(r0 + 3) * SA_STRIDE + k]);

        const u64* wn = reinterpret_cast<const u64*>(sWn + k * CDIM + c0);
        const u64* wr = reinterpret_cast<const u64*>(sWr + k * CDIM + c0);
        u64 n0 = wn[0], n1 = wn[1], n2 = wn[2], n3 = wn[3];
        u64 q0 = wr[0], q1 = wr[1], q2 = wr[2], q3 = wr[3];

        fma2(accT[0][0], a0, n0); fma2(accT[0][1], a0, n1); fma2(accT[0][2], a0, n2); fma2(accT[0][3], a0, n3);
        fma2(accT[1][0], a1, n0); fma2(accT[1][1], a1, n1); fma2(accT[1][2], a1, n2); fma2(accT[1][3], a1, n3);
        fma2(accT[2][0], a2, n0); fma2(accT[2][1], a2, n1); fma2(accT[2][2], a2, n2); fma2(accT[2][3], a2, n3);
        fma2(accT[3][0], a3, n0); fma2(accT[3][1], a3, n1); fma2(accT[3][2], a3, n2); fma2(accT[3][3], a3, n3);

        fma2(accR[0][0], a0, q0); fma2(accR[0][1], a0, q1); fma2(accR[0][2], a0, q2); fma2(accR[0][3], a0, q3);
        fma2(accR[1][0], a1, q0); fma2(accR[1][1], a1, q1); fma2(accR[1][2], a1, q2); fma2(accR[1][3], a1, q3);
        fma2(accR[2][0], a2, q0); fma2(accR[2][1], a2, q1); fma2(accR[2][2], a2, q2); fma2(accR[2][3], a2, q3);
        fma2(accR[3][0], a3, q0); fma2(accR[3][1], a3, q1); fma2(accR[3][2], a3, q2); fma2(accR[3][3], a3, q3);
    }

#pragma unroll
    for (int r = 0; r < 4; r++) {
        const int grow = rowBase + r0 + r;
        if (grow < N) {
            ulonglong2 t0, t1, h0, h1;
            t0.x = accT[r][0]; t0.y = accT[r][1]; t1.x = accT[r][2]; t1.y = accT[r][3];
            h0.x = accR[r][0]; h0.y = accR[r][1]; h1.x = accR[r][2]; h1.y = accR[r][3];
            *reinterpret_cast<ulonglong2*>(T + (size_t)grow * CDIM + c0)     = t0;
            *reinterpret_cast<ulonglong2*>(T + (size_t)grow * CDIM + c0 + 4) = t1;
            *reinterpret_cast<ulonglong2*>(H + (size_t)grow * CDIM + c0)     = h0;
            *reinterpret_cast<ulonglong2*>(H + (size_t)grow * CDIM + c0 + 4) = h1;
        }
    }
}

// ---------------- launch ----------------
extern "C" void kernel_launch(void* const* d_in, const int* in_sizes, int n_in,
                              void* d_out, int out_size)
{
    const float* x    = (const float*)d_in[0];
    const float* W1r  = (const float*)d_in[1];
    const float* W1n  = (const float*)d_in[2];
    const float* b1   = (const float*)d_in[3];
    const float* W2r  = (const float*)d_in[4];
    const float* W2n  = (const float*)d_in[5];
    const float* b2   = (const float*)d_in[6];
    const int*   psrc = (const int*)d_in[7];
    const int*   pdst = (const int*)d_in[8];
    const float* patt = (const float*)d_in[9];
    const int*   csrc = (const int*)d_in[10];
    const int*   cdst = (const int*)d_in[11];
    const float* catt = (const float*)d_in[12];
    const int*   usrc = (const int*)d_in[13];
    const int*   udst = (const int*)d_in[14];
    const float* uatt = (const float*)d_in[15];

    const int Ep = in_sizes[7];
    const int Ec = in_sizes[10];
    const int Eu = in_sizes[13];

    float* out = (float*)d_out;

    float *xc, *tb, *hb;
    cudaGetSymbolAddress((void**)&xc, g_xc);
    cudaGetSymbolAddress((void**)&tb, g_t);
    cudaGetSymbolAddress((void**)&hb, g_h);

    const int xc4  = NCC * CDIM / 4;
    const int out4 = out_size / 4;

    zero_kernel<<<(xc4 + 255) / 256, 256>>>((float4*)xc, xc4);
    zero_kernel<<<(out4 + 255) / 256, 256>>>((float4*)out, out4);

    // pool
    scatter_w<<<(int)(((long long)Ep * 16 + 255) / 256), 256>>>(x, psrc, pdst, patt, xc, Ep);

    // layer 1
    dual_gemm<<<(NCC + ROWS_PER_BLK - 1) / ROWS_PER_BLK, 256>>>(xc, W1n, W1r, b1, tb, hb, NCC);
    scatter_w<<<(int)(((long long)Ec * 16 + 255) / 256), 256>>>(tb, csrc, cdst, catt, hb, Ec);

    // layer 2
    dual_gemm<<<(NCC + ROWS_PER_BLK - 1) / ROWS_PER_BLK, 256>>>(hb, W2n, W2r, b2, tb, xc, NCC);
    scatter_w<<<(int)(((long long)Ec * 16 + 255) / 256), 256>>>(tb, csrc, cdst, catt, xc, Ec);

    // unpool
    scatter_w<<<(int)(((long long)Eu * 16 + 255) / 256), 256>>>(xc, usrc, udst, uatt, out, Eu);
}

// round 3
// speedup vs baseline: 1.8575x; 1.2325x over previous
#include <cuda_runtime.h>
#include <cstdint>

#define NCC   100000   // n_coarse
#define NFF   400000   // n_fine
#define CDIM  64
#define EPMAX 1200000
#define ECMAX 1600000
#define EUMAX 1200000

typedef unsigned long long u64;

// ---------------- scratch ----------------
__device__ float g_xc[(size_t)NCC * CDIM];
__device__ float g_t [(size_t)NCC * CDIM];
__device__ float g_h [(size_t)NCC * CDIM];

// CSR build scratch
__device__ int  g_pool_cnt[NCC + 1];
__device__ int  g_pool_off[NCC + 1];
__device__ int  g_pool_cur[NCC];
__device__ int2 g_pool_edges[EPMAX];

__device__ int  g_conv_cnt[NCC + 1];
__device__ int  g_conv_off[NCC + 1];
__device__ int  g_conv_cur[NCC];
__device__ int2 g_conv_edges[ECMAX];

__device__ int  g_unp_cnt[NFF + 1];
__device__ int  g_unp_off[NFF + 1];
__device__ int  g_unp_cur[NFF];
__device__ int2 g_unp_edges[EUMAX];

__device__ int  g_bsum[3 * 512];

// ---------------- helpers ----------------
__device__ __forceinline__ u64 pack2(float x) {
    u64 r;
    asm("mov.b64 %0, {%1, %1};" : "=l"(r) : "f"(x));
    return r;
}
__device__ __forceinline__ void fma2(u64& d, u64 a, u64 b) {
    asm("fma.rn.f32x2 %0, %1, %2, %0;" : "+l"(d) : "l"(a), "l"(b));
}

// ---------------- small utility kernels ----------------
__global__ void zero_int(int* __restrict__ p, int n) {
    int i = blockIdx.x * blockDim.x + threadIdx.x;
    if (i < n) p[i] = 0;
}

__global__ void hist_kernel(const int* __restrict__ dst, int* __restrict__ cnt, int E) {
    int i = blockIdx.x * blockDim.x + threadIdx.x;
    if (i < E) atomicAdd(&cnt[dst[i]], 1);
}

// exclusive scan over n elements, 1024-wide blocks; block sums to bsum
__global__ void scan_block(const int* __restrict__ cnt, int* __restrict__ off,
                           int* __restrict__ bsum, int n) {
    __shared__ int sh[1024];
    int tid = threadIdx.x;
    int i = blockIdx.x * 1024 + tid;
    int v = (i < n) ? cnt[i] : 0;
    sh[tid] = v;
    __syncthreads();
#pragma unroll
    for (int d = 1; d < 1024; d <<= 1) {
        int t = (tid >= d) ? sh[tid - d] : 0;
        __syncthreads();
        sh[tid] += t;
        __syncthreads();
    }
    if (i < n) off[i] = sh[tid] - v;   // exclusive
    if (tid == 1023) bsum[blockIdx.x] = sh[1023];
}

// exclusive scan (in place) of nb block sums; single block, nb <= 1024
__global__ void scan_aux(int* __restrict__ bsum, int nb) {
    __shared__ int sh[1024];
    int tid = threadIdx.x;
    int v = (tid < nb) ? bsum[tid] : 0;
    sh[tid] = v;
    __syncthreads();
#pragma unroll
    for (int d = 1; d < 1024; d <<= 1) {
        int t = (tid >= d) ? sh[tid - d] : 0;
        __syncthreads();
        sh[tid] += t;
        __syncthreads();
    }
    if (tid < nb) bsum[tid] = sh[tid] - v;  // exclusive
}

// add block offsets, also initialize cursor (size n-1; cursor covers nodes only)
__global__ void scan_add(int* __restrict__ off, const int* __restrict__ bsum,
                         int* __restrict__ cursor, int n) {
    int i = blockIdx.x * blockDim.x + threadIdx.x;
    if (i < n) {
        int o = off[i] + bsum[i >> 10];
        off[i] = o;
        if (i < n - 1) cursor[i] = o;
    }
}

// scatter edge payloads into dst-sorted order
__global__ void permute_kernel(const int* __restrict__ src, const int* __restrict__ dst,
                               const float* __restrict__ attr, int* __restrict__ cursor,
                               int2* __restrict__ edges, int E) {
    int i = blockIdx.x * blockDim.x + threadIdx.x;
    if (i < E) {
        int p = atomicAdd(&cursor[dst[i]], 1);
        edges[p] = make_int2(src[i], __float_as_int(attr[i]));
    }
}

// ---------------- CSR gather: out[node] (+)= sum_e attr_e * feat[src_e] ----------------
// 16 threads per node (one float4 column each), register accumulation, single store.
template <bool INIT_FROM_OUT>
__global__ void __launch_bounds__(256) gather_kernel(
    const float* __restrict__ feat,
    const int2*  __restrict__ edges,
    const int*   __restrict__ off,
    float*       __restrict__ outp,
    int n)
{
    int idx = blockIdx.x * blockDim.x + threadIdx.x;
    int node = idx >> 4;
    if (node >= n) return;
    int q = (idx & 15) << 2;

    int e0 = __ldg(off + node);
    int e1 = __ldg(off + node + 1);

    float4 acc;
    float* orow = outp + (size_t)node * CDIM + q;
    if (INIT_FROM_OUT) acc = *reinterpret_cast<const float4*>(orow);
    else               acc = make_float4(0.f, 0.f, 0.f, 0.f);

#pragma unroll 2
    for (int e = e0; e < e1; e++) {
        int2 ed = __ldg(edges + e);
        float w = __int_as_float(ed.y);
        float4 v = __ldg(reinterpret_cast<const float4*>(feat + (size_t)ed.x * CDIM + q));
        acc.x = fmaf(w, v.x, acc.x);
        acc.y = fmaf(w, v.y, acc.y);
        acc.z = fmaf(w, v.z, acc.z);
        acc.w = fmaf(w, v.w, acc.w);
    }
    *reinterpret_cast<float4*>(orow) = acc;
}

// ---------------- fused dual GEMM with 4-row register blocking ----------------
#define ROWS_PER_BLK 128
#define SA_STRIDE    68

__global__ void __launch_bounds__(256, 2) dual_gemm(
    const float* __restrict__ A,
    const float* __restrict__ Wn,
    const float* __restrict__ Wr,
    const float* __restrict__ bias,
    float* __restrict__ T,
    float* __restrict__ H,
    int N)
{
    __shared__ float sWn[CDIM * CDIM];
    __shared__ float sWr[CDIM * CDIM];
    __shared__ float sA[ROWS_PER_BLK * SA_STRIDE];

    const int t = threadIdx.x;

    {
        const float4* Wn4 = reinterpret_cast<const float4*>(Wn);
        const float4* Wr4 = reinterpret_cast<const float4*>(Wr);
        float4* sWn4 = reinterpret_cast<float4*>(sWn);
        float4* sWr4 = reinterpret_cast<float4*>(sWr);
#pragma unroll
        for (int i = 0; i < 4; i++) {
            sWn4[t + 256 * i] = Wn4[t + 256 * i];
            sWr4[t + 256 * i] = Wr4[t + 256 * i];
        }
    }

    const int rowBase = blockIdx.x * ROWS_PER_BLK;
#pragma unroll
    for (int i = 0; i < 8; i++) {
        int idx = t + 256 * i;
        int row = idx >> 4;
        int kc  = (idx & 15) * 4;
        float4 a;
        if (rowBase + row < N)
            a = *reinterpret_cast<const float4*>(A + (size_t)(rowBase + row) * CDIM + kc);
        else
            a = make_float4(0.f, 0.f, 0.f, 0.f);
        *reinterpret_cast<float4*>(sA + row * SA_STRIDE + kc) = a;
    }
    __syncthreads();

    const int c0 = (t & 7) * 8;
    const int r0 = (t >> 3) * 4;

    u64 accT[4][4], accR[4][4];
    {
        const u64* b2 = reinterpret_cast<const u64*>(bias + c0);
        u64 bv[4];
#pragma unroll
        for (int j = 0; j < 4; j++) bv[j] = b2[j];
#pragma unroll
        for (int r = 0; r < 4; r++)
#pragma unroll
            for (int j = 0; j < 4; j++) { accT[r][j] = 0ull; accR[r][j] = bv[j]; }
    }

#pragma unroll 8
    for (int k = 0; k < CDIM; k++) {
        u64 a0 = pack2(sA[(r0 + 0) * SA_STRIDE + k]);
        u64 a1 = pack2(sA[(r0 + 1) * SA_STRIDE + k]);
        u64 a2 = pack2(sA[(r0 + 2) * SA_STRIDE + k]);
        u64 a3 = pack2(sA[(r0 + 3) * SA_STRIDE + k]);

        const u64* wn = reinterpret_cast<const u64*>(sWn + k * CDIM + c0);
        const u64* wr = reinterpret_cast<const u64*>(sWr + k * CDIM + c0);
        u64 n0 = wn[0], n1 = wn[1], n2 = wn[2], n3 = wn[3];
        u64 q0 = wr[0], q1 = wr[1], q2 = wr[2], q3 = wr[3];

        fma2(accT[0][0], a0, n0); fma2(accT[0][1], a0, n1); fma2(accT[0][2], a0, n2); fma2(accT[0][3], a0, n3);
        fma2(accT[1][0], a1, n0); fma2(accT[1][1], a1, n1); fma2(accT[1][2], a1, n2); fma2(accT[1][3], a1, n3);
        fma2(accT[2][0], a2, n0); fma2(accT[2][1], a2, n1); fma2(accT[2][2], a2, n2); fma2(accT[2][3], a2, n3);
        fma2(accT[3][0], a3, n0); fma2(accT[3][1], a3, n1); fma2(accT[3][2], a3, n2); fma2(accT[3][3], a3, n3);

        fma2(accR[0][0], a0, q0); fma2(accR[0][1], a0, q1); fma2(accR[0][2], a0, q2); fma2(accR[0][3], a0, q3);
        fma2(accR[1][0], a1, q0); fma2(accR[1][1], a1, q1); fma2(accR[1][2], a1, q2); fma2(accR[1][3], a1, q3);
        fma2(accR[2][0], a2, q0); fma2(accR[2][1], a2, q1); fma2(accR[2][2], a2, q2); fma2(accR[2][3], a2, q3);
        fma2(accR[3][0], a3, q0); fma2(accR[3][1], a3, q1); fma2(accR[3][2], a3, q2); fma2(accR[3][3], a3, q3);
    }

#pragma unroll
    for (int r = 0; r < 4; r++) {
        const int grow = rowBase + r0 + r;
        if (grow < N) {
            ulonglong2 t0, t1, h0, h1;
            t0.x = accT[r][0]; t0.y = accT[r][1]; t1.x = accT[r][2]; t1.y = accT[r][3];
            h0.x = accR[r][0]; h0.y = accR[r][1]; h1.x = accR[r][2]; h1.y = accR[r][3];
            *reinterpret_cast<ulonglong2*>(T + (size_t)grow * CDIM + c0)     = t0;
            *reinterpret_cast<ulonglong2*>(T + (size_t)grow * CDIM + c0 + 4) = t1;
            *reinterpret_cast<ulonglong2*>(H + (size_t)grow * CDIM + c0)     = h0;
            *reinterpret_cast<ulonglong2*>(H + (size_t)grow * CDIM + c0 + 4) = h1;
        }
    }
}

// ---------------- host-side CSR build helper ----------------
static void build_csr(const int* src, const int* dst, const float* attr, int E,
                      int* cnt, int* off, int* cur, int2* edges, int* bsum, int nNodes)
{
    const int n1 = nNodes + 1;
    zero_int<<<(n1 + 255) / 256, 256>>>(cnt, n1);
    hist_kernel<<<(E + 255) / 256, 256>>>(dst, cnt, E);
    int nb = (n1 + 1023) / 1024;
    scan_block<<<nb, 1024>>>(cnt, off, bsum, n1);
    scan_aux<<<1, 1024>>>(bsum, nb);
    scan_add<<<(n1 + 255) / 256, 256>>>(off, bsum, cur, n1);
    permute_kernel<<<(E + 255) / 256, 256>>>(src, dst, attr, cur, edges, E);
}

// ---------------- launch ----------------
extern "C" void kernel_launch(void* const* d_in, const int* in_sizes, int n_in,
                              void* d_out, int out_size)
{
    const float* x    = (const float*)d_in[0];
    const float* W1r  = (const float*)d_in[1];
    const float* W1n  = (const float*)d_in[2];
    const float* b1   = (const float*)d_in[3];
    const float* W2r  = (const float*)d_in[4];
    const float* W2n  = (const float*)d_in[5];
    const float* b2   = (const float*)d_in[6];
    const int*   psrc = (const int*)d_in[7];
    const int*   pdst = (const int*)d_in[8];
    const float* patt = (const float*)d_in[9];
    const int*   csrc = (const int*)d_in[10];
    const int*   cdst = (const int*)d_in[11];
    const float* catt = (const float*)d_in[12];
    const int*   usrc = (const int*)d_in[13];
    const int*   udst = (const int*)d_in[14];
    const float* uatt = (const float*)d_in[15];

    const int Ep = in_sizes[7];
    const int Ec = in_sizes[10];
    const int Eu = in_sizes[13];

    float* out = (float*)d_out;

    float *xc, *tb, *hb;
    cudaGetSymbolAddress((void**)&xc, g_xc);
    cudaGetSymbolAddress((void**)&tb, g_t);
    cudaGetSymbolAddress((void**)&hb, g_h);

    int *pcnt, *poff, *pcur, *ccnt, *coff, *ccur, *ucnt, *uoff, *ucur, *bsum;
    int2 *pedg, *cedg, *uedg;
    cudaGetSymbolAddress((void**)&pcnt, g_pool_cnt);
    cudaGetSymbolAddress((void**)&poff, g_pool_off);
    cudaGetSymbolAddress((void**)&pcur, g_pool_cur);
    cudaGetSymbolAddress((void**)&pedg, g_pool_edges);
    cudaGetSymbolAddress((void**)&ccnt, g_conv_cnt);
    cudaGetSymbolAddress((void**)&coff, g_conv_off);
    cudaGetSymbolAddress((void**)&ccur, g_conv_cur);
    cudaGetSymbolAddress((void**)&cedg, g_conv_edges);
    cudaGetSymbolAddress((void**)&ucnt, g_unp_cnt);
    cudaGetSymbolAddress((void**)&uoff, g_unp_off);
    cudaGetSymbolAddress((void**)&ucur, g_unp_cur);
    cudaGetSymbolAddress((void**)&uedg, g_unp_edges);
    cudaGetSymbolAddress((void**)&bsum, g_bsum);

    // build CSR for all three edge sets
    build_csr(psrc, pdst, patt, Ep, pcnt, poff, pcur, pedg, bsum,        NCC);
    build_csr(csrc, cdst, catt, Ec, ccnt, coff, ccur, cedg, bsum + 512,  NCC);
    build_csr(usrc, udst, uatt, Eu, ucnt, uoff, ucur, uedg, bsum + 1024, NFF);

    const int gthreadsC = NCC * 16;
    const int gthreadsF = NFF * 16;

    // pool: xc = gather(x)
    gather_kernel<false><<<(gthreadsC + 255) / 256, 256>>>(x, pedg, poff, xc, NCC);

    // layer 1
    dual_gemm<<<(NCC + ROWS_PER_BLK - 1) / ROWS_PER_BLK, 256>>>(xc, W1n, W1r, b1, tb, hb, NCC);
    gather_kernel<true><<<(gthreadsC + 255) / 256, 256>>>(tb, cedg, coff, hb, NCC);

    // layer 2
    dual_gemm<<<(NCC + ROWS_PER_BLK - 1) / ROWS_PER_BLK, 256>>>(hb, W2n, W2r, b2, tb, xc, NCC);
    gather_kernel<true><<<(gthreadsC + 255) / 256, 256>>>(tb, cedg, coff, xc, NCC);

    // unpool: out = gather(xc)
    gather_kernel<false><<<(gthreadsF + 255) / 256, 256>>>(xc, uedg, uoff, out, NFF);
}